// round 15
// baseline (speedup 1.0000x reference)
#include <cuda_runtime.h>
#include <cuda_bf16.h>
#include <stdint.h>

// Problem constants
#define N_ROWS 4096
#define C_CLS  1000
#define D_DIM  1024
#define NC_PER_T 4096000u          // N*C
#define SIG_OFF  4096000           // sigma offset in d_out (after mu_out)

// mu scratch (sigma lives in d_out directly)
__device__ float g_mu[N_ROWS * C_CLS];

// ---------------------------------------------------------------------------
// Threefry2x32-20, key (0, 42), PARTITIONABLE mode: ctr=(0,i), xor-fold out.
// ---------------------------------------------------------------------------
__device__ __forceinline__ uint32_t tf_fold(uint32_t ctr) {
    const uint32_t ks0 = 0u;
    const uint32_t ks1 = 42u;
    const uint32_t ks2 = 0x1BD11BDAu ^ 0u ^ 42u;
    uint32_t x0 = 0u + ks0;
    uint32_t x1 = ctr + ks1;
#define TFR(r) { x0 += x1; x1 = __funnelshift_l(x1, x1, (r)); x1 ^= x0; }
    TFR(13) TFR(15) TFR(26) TFR(6)
    x0 += ks1; x1 += ks2 + 1u;
    TFR(17) TFR(29) TFR(16) TFR(24)
    x0 += ks2; x1 += ks0 + 2u;
    TFR(13) TFR(15) TFR(26) TFR(6)
    x0 += ks0; x1 += ks1 + 3u;
    TFR(17) TFR(29) TFR(16) TFR(24)
    x0 += ks1; x1 += ks2 + 4u;
    TFR(13) TFR(15) TFR(26) TFR(6)
    x0 += ks2; x1 += ks0 + 5u;
#undef TFR
    return x0 ^ x1;
}

// bits -> uniform(-0.99999994, 1) -> erfinv(u).  sqrt(2)*log2(e) folded into
// caller's sg2/mu2.  Clamp removed: fmaf(f,2,-0.99999994) >= -0.99999994 for
// f in [0,1) (equality at f=0; RN never rounds below the bound).
__device__ __forceinline__ float bits_to_eps(uint32_t b) {
    float f = __uint_as_float((b >> 9) | 0x3f800000u) - 1.0f;   // [0,1)
    float u = fmaf(f, 2.0f, -0.99999994f);
    return erfinvf(u);
}

// ===========================================================================
// GEMM v7: mma.sync m16n8k8 tf32, 3-stage ring, K chunks of 16,
// SINGLE __syncthreads per chunk (refill target (t+2)%3 was consumed at
// iter t-1, so it is free right after the top-of-loop barrier).
// 128x128 tile, 8 warps 4(M)x2(N), warp tile 32x64.
// smem row stride 20 floats (banks 20g+tg cover all 32 -> conflict-free).
// 60 KB dyn smem -> 2 CTAs/SM preserved.
// ===========================================================================
#define CHUNK_K 16
#define NCHUNK  (D_DIM / CHUNK_K)     // 64
#define RST     20                    // smem row stride in floats
#define MAT_F   (128 * RST)           // 2560 floats per matrix per stage
#define STAGE_F (2 * MAT_F)           // 5120 floats (20480 B) per stage
#define NSTAGE  3

__device__ __forceinline__ void mma_tf32(float* c, const uint32_t* a, const uint32_t* b) {
    asm volatile(
        "mma.sync.aligned.m16n8k8.row.col.f32.tf32.tf32.f32 "
        "{%0,%1,%2,%3}, {%4,%5,%6,%7}, {%8,%9}, {%0,%1,%2,%3};"
        : "+f"(c[0]), "+f"(c[1]), "+f"(c[2]), "+f"(c[3])
        : "r"(a[0]), "r"(a[1]), "r"(a[2]), "r"(a[3]), "r"(b[0]), "r"(b[1]));
}

__global__ __launch_bounds__(256) void gemm_kernel(
    const float* __restrict__ X, const float* __restrict__ W,
    float* __restrict__ out)
{
    extern __shared__ __align__(16) float dynsm[];   // NSTAGE * STAGE_F

    const int tid = threadIdx.x;
    const int wid = tid >> 5;
    const int lane = tid & 31;
    const int bm = blockIdx.y * 128;
    const int bn = blockIdx.x * 128;
    const int wm = wid >> 1;
    const int wn = wid & 1;
    const int g  = lane >> 2;
    const int tg = lane & 3;

    // loader: per stage, per matrix: 128 rows x 4 float4 = 512 cp.asyncs;
    // 2 matrices / 256 threads = 2 A + 2 B per thread.
    // idx = tid + p*256 (p=0..1): row = idx>>2 (0..127), ch = idx&3.
#define ISSUE(t, stg) { \
    const int kbase = (t) * CHUNK_K; \
    _Pragma("unroll") \
    for (int p = 0; p < 2; ++p) { \
        const int idx = tid + p * 256; \
        const int row = idx >> 2, ch = idx & 3; \
        uint32_t dA = smem_base + (uint32_t)(((stg) * STAGE_F + row * RST + ch * 4) * 4); \
        const float* sA = X + (size_t)(bm + row) * D_DIM + kbase + ch * 4; \
        asm volatile("cp.async.ca.shared.global [%0], [%1], 16;" :: "r"(dA), "l"(sA)); \
        uint32_t dB = smem_base + (uint32_t)(((stg) * STAGE_F + MAT_F + row * RST + ch * 4) * 4); \
        const int wr = bn + row; \
        const float* sB = W + (size_t)(wr < 2000 ? wr : 1999) * D_DIM + kbase + ch * 4; \
        const int bb = (wr < 2000) ? 16 : 0; \
        asm volatile("cp.async.ca.shared.global [%0], [%1], 16, %2;" :: "r"(dB), "l"(sB), "r"(bb)); \
    } \
    asm volatile("cp.async.commit_group;"); \
}

    const uint32_t smem_base = (uint32_t)__cvta_generic_to_shared(dynsm);

    float acc[2][8][4];
#pragma unroll
    for (int ma = 0; ma < 2; ++ma)
#pragma unroll
        for (int na = 0; na < 8; ++na)
#pragma unroll
            for (int r = 0; r < 4; ++r) acc[ma][na][r] = 0.f;

    ISSUE(0, 0)
    ISSUE(1, 1)

#pragma unroll 1
    for (int t = 0; t < NCHUNK; ++t) {
        const int stg = t % NSTAGE;
        if (t < NCHUNK - 1) { asm volatile("cp.async.wait_group 1;"); }
        else                { asm volatile("cp.async.wait_group 0;"); }
        __syncthreads();
        // refill (t+2) into stage (t+2)%3 == (t-1)%3: consumed at iter t-1,
        // and the barrier above guarantees all warps have left it.
        if (t + 2 < NCHUNK) { ISSUE(t + 2, (t + 2) % NSTAGE) }

        const float* Ab = dynsm + stg * STAGE_F + (wm * 32 + g) * RST + tg;
        const float* Bb = dynsm + stg * STAGE_F + MAT_F + (wn * 64 + g) * RST + tg;

#pragma unroll
        for (int ks = 0; ks < 2; ++ks) {
            uint32_t a[2][4], b[8][2];
#pragma unroll
            for (int ma = 0; ma < 2; ++ma) {
                const float* p = Ab + ma * 16 * RST + ks * 8;
                a[ma][0] = __float_as_uint(p[0]);
                a[ma][1] = __float_as_uint(p[8 * RST]);
                a[ma][2] = __float_as_uint(p[4]);
                a[ma][3] = __float_as_uint(p[8 * RST + 4]);
            }
#pragma unroll
            for (int na = 0; na < 8; ++na) {
                const float* p = Bb + na * 8 * RST + ks * 8;
                b[na][0] = __float_as_uint(p[0]);
                b[na][1] = __float_as_uint(p[4]);
            }
#pragma unroll
            for (int ma = 0; ma < 2; ++ma)
#pragma unroll
                for (int na = 0; na < 8; ++na)
                    mma_tf32(acc[ma][na], a[ma], b[na]);
        }
        // no trailing __syncthreads: next iteration's refill targets a stage
        // untouched by this iteration's reads.
    }
#undef ISSUE

#pragma unroll
    for (int ma = 0; ma < 2; ++ma) {
        const int row0 = bm + wm * 32 + ma * 16 + g;
#pragma unroll
        for (int na = 0; na < 8; ++na) {
            const int j = bn + wn * 64 + na * 8 + 2 * tg;
#pragma unroll
            for (int h = 0; h < 2; ++h) {
                const int row = row0 + h * 8;
                const float v0 = acc[ma][na][2 * h + 0];
                const float v1 = acc[ma][na][2 * h + 1];
                if (j < 1000) {
                    float2 o = make_float2(v0, v1);
                    *(float2*)(g_mu + (size_t)row * C_CLS + j) = o;
                } else if (j < 2000) {
                    float2 o = make_float2(__expf(0.5f * v0), __expf(0.5f * v1));
                    *(float2*)(out + SIG_OFF + (size_t)row * C_CLS + (j - 1000)) = o;
                }
            }
        }
    }
}

// ---------------------------------------------------------------------------
// Kernel B: per-n sampling + softmax + mean + exp (exact R14, 424us).
// ---------------------------------------------------------------------------
#define LOG2E 1.44269504088896f

__global__ __launch_bounds__(256, 6) void sample_kernel(float* __restrict__ out)
{
    __shared__ float wsum[2][2][8];   // [buf][pair 0/1][warp]

    const int n = blockIdx.x;
    const int tid = threadIdx.x;
    const int warp = tid >> 5;
    const int lane = tid & 31;
    const int c0 = tid << 2;
    const bool active = (c0 < C_CLS);
    const float* g_sigma = out + SIG_OFF;

    float mu2[4] = {0.f, 0.f, 0.f, 0.f};
    float sg2[4] = {0.f, 0.f, 0.f, 0.f};
    if (active) {
        float4 m4 = *(const float4*)(g_mu + (size_t)n * C_CLS + c0);
        float4 s4 = *(const float4*)(g_sigma + (size_t)n * C_CLS + c0);
        mu2[0] = m4.x * LOG2E; mu2[1] = m4.y * LOG2E;
        mu2[2] = m4.z * LOG2E; mu2[3] = m4.w * LOG2E;
        const float k = 1.41421356f * LOG2E;
        sg2[0] = s4.x * k; sg2[1] = s4.y * k;
        sg2[2] = s4.z * k; sg2[3] = s4.w * k;
    }

    float a0 = 0.f, a1 = 0.f, a2 = 0.f, a3 = 0.f;

#pragma unroll 1
    for (int tp = 0; tp < 16; ++tp) {
        const int buf = tp & 1;
        float q0[4], q1[4];
        float s0 = 0.f, s1 = 0.f;
        if (active) {
            const uint32_t ib = (uint32_t)tp * NC_PER_T + (uint32_t)n * 1000u + (uint32_t)c0;
#pragma unroll
            for (int j = 0; j < 4; ++j) {
                float e0 = bits_to_eps(tf_fold(ib + j));                  // t = tp
                float e1 = bits_to_eps(tf_fold(ib + j + 16u * NC_PER_T)); // t = tp+16
                q0[j] = exp2f(fmaf(sg2[j], e0, mu2[j]));
                q1[j] = exp2f(fmaf(sg2[j], e1, mu2[j]));
                s0 += q0[j]; s1 += q1[j];
            }
        } else {
#pragma unroll
            for (int j = 0; j < 4; ++j) { q0[j] = 0.f; q1[j] = 0.f; }
        }
#pragma unroll
        for (int off = 16; off; off >>= 1) {
            s0 += __shfl_xor_sync(0xffffffffu, s0, off);
            s1 += __shfl_xor_sync(0xffffffffu, s1, off);
        }
        if (lane == 0) {
            wsum[buf][0][warp] = s0;
            wsum[buf][1][warp] = s1;
        }
        __syncthreads();

        float t0 = 0.f, t1 = 0.f;
#pragma unroll
        for (int w = 0; w < 8; ++w) {
            t0 += wsum[buf][0][w];
            t1 += wsum[buf][1][w];
        }
        float inv0, inv1;
        asm("rcp.approx.ftz.f32 %0, %1;" : "=f"(inv0) : "f"(t0));
        asm("rcp.approx.ftz.f32 %0, %1;" : "=f"(inv1) : "f"(t1));

        a0 = fmaf(q0[0], inv0, a0); a0 = fmaf(q1[0], inv1, a0);
        a1 = fmaf(q0[1], inv0, a1); a1 = fmaf(q1[1], inv1, a1);
        a2 = fmaf(q0[2], inv0, a2); a2 = fmaf(q1[2], inv1, a2);
        a3 = fmaf(q0[3], inv0, a3); a3 = fmaf(q1[3], inv1, a3);
    }

    if (active) {
        float4 o;
        o.x = __expf(a0 * 0.03125f);
        o.y = __expf(a1 * 0.03125f);
        o.z = __expf(a2 * 0.03125f);
        o.w = __expf(a3 * 0.03125f);
        *(float4*)(out + (size_t)n * C_CLS + c0) = o;
    }
}

// ---------------------------------------------------------------------------
extern "C" void kernel_launch(void* const* d_in, const int* in_sizes, int n_in,
                              void* d_out, int out_size)
{
    const float* X = (const float*)d_in[0];   // (4096, 1024)
    const float* W = (const float*)d_in[1];   // (2000, 1024)
    float* out = (float*)d_out;               // mu_out (4096,1000) ++ sigma (4096,1000)

    const int gemm_smem = NSTAGE * STAGE_F * 4;   // 61440 B -> 2 CTAs/SM
    cudaFuncSetAttribute(gemm_kernel,
                         cudaFuncAttributeMaxDynamicSharedMemorySize, gemm_smem);
    gemm_kernel<<<dim3(16, 32), 256, gemm_smem>>>(X, W, out);
    sample_kernel<<<N_ROWS, 256>>>(out);
}

// round 16
// speedup vs baseline: 1.1076x; 1.1076x over previous
#include <cuda_runtime.h>
#include <cuda_bf16.h>
#include <stdint.h>

// Problem constants
#define N_ROWS 4096
#define C_CLS  1000
#define D_DIM  1024
#define NC_PER_T 4096000u          // N*C
#define SIG_OFF  4096000           // sigma offset in d_out (after mu_out)

// mu scratch (sigma lives in d_out directly)
__device__ float g_mu[N_ROWS * C_CLS];

// ---------------------------------------------------------------------------
// Threefry2x32-20, key (0, 42), PARTITIONABLE mode: ctr=(0,i), xor-fold out.
// Pure SHF rotates (proven fastest; all IMAD-offload variants regressed).
// ---------------------------------------------------------------------------
__device__ __forceinline__ uint32_t tf_fold(uint32_t ctr) {
    const uint32_t ks0 = 0u;
    const uint32_t ks1 = 42u;
    const uint32_t ks2 = 0x1BD11BDAu ^ 0u ^ 42u;
    uint32_t x0 = 0u + ks0;
    uint32_t x1 = ctr + ks1;
#define TFR(r) { x0 += x1; x1 = __funnelshift_l(x1, x1, (r)); x1 ^= x0; }
    TFR(13) TFR(15) TFR(26) TFR(6)
    x0 += ks1; x1 += ks2 + 1u;
    TFR(17) TFR(29) TFR(16) TFR(24)
    x0 += ks2; x1 += ks0 + 2u;
    TFR(13) TFR(15) TFR(26) TFR(6)
    x0 += ks0; x1 += ks1 + 3u;
    TFR(17) TFR(29) TFR(16) TFR(24)
    x0 += ks1; x1 += ks2 + 4u;
    TFR(13) TFR(15) TFR(26) TFR(6)
    x0 += ks2; x1 += ks0 + 5u;
#undef TFR
    return x0 ^ x1;
}

// bits -> uniform(-0.99999994, 1) -> erfinv(u).  sqrt(2)*log2(e) folded into
// caller's sg2/mu2.  Clamp removed: fmaf(f,2,-0.99999994) >= -0.99999994 for
// f in [0,1) (equality at f=0; RN never rounds below the bound).
__device__ __forceinline__ float bits_to_eps(uint32_t b) {
    float f = __uint_as_float((b >> 9) | 0x3f800000u) - 1.0f;   // [0,1)
    float u = fmaf(f, 2.0f, -0.99999994f);
    return erfinvf(u);
}

// ===========================================================================
// GEMM (exact R14 config, proven ~121us): mma.sync m16n8k8 tf32.
// 128x128 tile, 8 warps 4(M)x2(N), warp tile 32x64 (2x8 atoms).
// K chunks of 32 (4 k8 steps), 2-stage cp.async (.ca), smem stride 36 floats.
// ===========================================================================
#define CHUNK_K 32
#define NCHUNK  (D_DIM / CHUNK_K)     // 32
#define RST     36                    // smem row stride in floats
#define MAT_F   (128 * RST)           // floats per matrix per stage (4608)
#define STAGE_F (2 * MAT_F)           // A + B per stage (9216 floats)

__device__ __forceinline__ void mma_tf32(float* c, const uint32_t* a, const uint32_t* b) {
    asm volatile(
        "mma.sync.aligned.m16n8k8.row.col.f32.tf32.tf32.f32 "
        "{%0,%1,%2,%3}, {%4,%5,%6,%7}, {%8,%9}, {%0,%1,%2,%3};"
        : "+f"(c[0]), "+f"(c[1]), "+f"(c[2]), "+f"(c[3])
        : "r"(a[0]), "r"(a[1]), "r"(a[2]), "r"(a[3]), "r"(b[0]), "r"(b[1]));
}

__global__ __launch_bounds__(256) void gemm_kernel(
    const float* __restrict__ X, const float* __restrict__ W,
    float* __restrict__ out)
{
    extern __shared__ __align__(16) float dynsm[];   // 2 * STAGE_F

    const int tid = threadIdx.x;
    const int wid = tid >> 5;
    const int lane = tid & 31;
    const int bm = blockIdx.y * 128;
    const int bn = blockIdx.x * 128;
    const int wm = wid >> 1;
    const int wn = wid & 1;
    const int g  = lane >> 2;
    const int tg = lane & 3;

#define ISSUE(t, stg) { \
    const int kbase = (t) * CHUNK_K; \
    _Pragma("unroll") \
    for (int p = 0; p < 4; ++p) { \
        const int idx = tid + p * 256; \
        const int row = idx >> 3, ch = idx & 7; \
        uint32_t dA = smem_base + (uint32_t)(((stg) * STAGE_F + row * RST + ch * 4) * 4); \
        const float* sA = X + (size_t)(bm + row) * D_DIM + kbase + ch * 4; \
        asm volatile("cp.async.ca.shared.global [%0], [%1], 16;" :: "r"(dA), "l"(sA)); \
        uint32_t dB = smem_base + (uint32_t)(((stg) * STAGE_F + MAT_F + row * RST + ch * 4) * 4); \
        const int wr = bn + row; \
        const float* sB = W + (size_t)(wr < 2000 ? wr : 1999) * D_DIM + kbase + ch * 4; \
        const int bb = (wr < 2000) ? 16 : 0; \
        asm volatile("cp.async.ca.shared.global [%0], [%1], 16, %2;" :: "r"(dB), "l"(sB), "r"(bb)); \
    } \
    asm volatile("cp.async.commit_group;"); \
}

    const uint32_t smem_base = (uint32_t)__cvta_generic_to_shared(dynsm);

    float acc[2][8][4];
#pragma unroll
    for (int ma = 0; ma < 2; ++ma)
#pragma unroll
        for (int na = 0; na < 8; ++na)
#pragma unroll
            for (int r = 0; r < 4; ++r) acc[ma][na][r] = 0.f;

    ISSUE(0, 0)
    ISSUE(1, 1)

#pragma unroll 1
    for (int t = 0; t < NCHUNK; ++t) {
        const int stg = t & 1;
        if (t < NCHUNK - 1) { asm volatile("cp.async.wait_group 1;"); }
        else                { asm volatile("cp.async.wait_group 0;"); }
        __syncthreads();

        const float* Ab = dynsm + stg * STAGE_F + (wm * 32 + g) * RST + tg;
        const float* Bb = dynsm + stg * STAGE_F + MAT_F + (wn * 64 + g) * RST + tg;

#pragma unroll
        for (int ks = 0; ks < 4; ++ks) {
            uint32_t a[2][4], b[8][2];
#pragma unroll
            for (int ma = 0; ma < 2; ++ma) {
                const float* p = Ab + ma * 16 * RST + ks * 8;
                a[ma][0] = __float_as_uint(p[0]);
                a[ma][1] = __float_as_uint(p[8 * RST]);
                a[ma][2] = __float_as_uint(p[4]);
                a[ma][3] = __float_as_uint(p[8 * RST + 4]);
            }
#pragma unroll
            for (int na = 0; na < 8; ++na) {
                const float* p = Bb + na * 8 * RST + ks * 8;
                b[na][0] = __float_as_uint(p[0]);
                b[na][1] = __float_as_uint(p[4]);
            }
#pragma unroll
            for (int ma = 0; ma < 2; ++ma)
#pragma unroll
                for (int na = 0; na < 8; ++na)
                    mma_tf32(acc[ma][na], a[ma], b[na]);
        }
        __syncthreads();
        if (t + 2 < NCHUNK) { ISSUE(t + 2, stg) }
    }
#undef ISSUE

#pragma unroll
    for (int ma = 0; ma < 2; ++ma) {
        const int row0 = bm + wm * 32 + ma * 16 + g;
#pragma unroll
        for (int na = 0; na < 8; ++na) {
            const int j = bn + wn * 64 + na * 8 + 2 * tg;
#pragma unroll
            for (int h = 0; h < 2; ++h) {
                const int row = row0 + h * 8;
                const float v0 = acc[ma][na][2 * h + 0];
                const float v1 = acc[ma][na][2 * h + 1];
                if (j < 1000) {
                    float2 o = make_float2(v0, v1);
                    *(float2*)(g_mu + (size_t)row * C_CLS + j) = o;
                } else if (j < 2000) {
                    float2 o = make_float2(__expf(0.5f * v0), __expf(0.5f * v1));
                    *(float2*)(out + SIG_OFF + (size_t)row * C_CLS + (j - 1000)) = o;
                }
            }
        }
    }
}

// ---------------------------------------------------------------------------
// Kernel B: per-n sampling + softmax + mean + exp (exact R14, ~424us).
// log2(e) pre-folded into mu2/sg2 so the inner exp is a bare exp2f.
// ---------------------------------------------------------------------------
#define LOG2E 1.44269504088896f

__global__ __launch_bounds__(256, 6) void sample_kernel(float* __restrict__ out)
{
    __shared__ float wsum[2][2][8];   // [buf][pair 0/1][warp]

    const int n = blockIdx.x;
    const int tid = threadIdx.x;
    const int warp = tid >> 5;
    const int lane = tid & 31;
    const int c0 = tid << 2;
    const bool active = (c0 < C_CLS);
    const float* g_sigma = out + SIG_OFF;

    float mu2[4] = {0.f, 0.f, 0.f, 0.f};
    float sg2[4] = {0.f, 0.f, 0.f, 0.f};
    if (active) {
        float4 m4 = *(const float4*)(g_mu + (size_t)n * C_CLS + c0);
        float4 s4 = *(const float4*)(g_sigma + (size_t)n * C_CLS + c0);
        mu2[0] = m4.x * LOG2E; mu2[1] = m4.y * LOG2E;
        mu2[2] = m4.z * LOG2E; mu2[3] = m4.w * LOG2E;
        const float k = 1.41421356f * LOG2E;
        sg2[0] = s4.x * k; sg2[1] = s4.y * k;
        sg2[2] = s4.z * k; sg2[3] = s4.w * k;
    }

    float a0 = 0.f, a1 = 0.f, a2 = 0.f, a3 = 0.f;

#pragma unroll 1
    for (int tp = 0; tp < 16; ++tp) {
        const int buf = tp & 1;
        float q0[4], q1[4];
        float s0 = 0.f, s1 = 0.f;
        if (active) {
            const uint32_t ib = (uint32_t)tp * NC_PER_T + (uint32_t)n * 1000u + (uint32_t)c0;
#pragma unroll
            for (int j = 0; j < 4; ++j) {
                float e0 = bits_to_eps(tf_fold(ib + j));                  // t = tp
                float e1 = bits_to_eps(tf_fold(ib + j + 16u * NC_PER_T)); // t = tp+16
                q0[j] = exp2f(fmaf(sg2[j], e0, mu2[j]));
                q1[j] = exp2f(fmaf(sg2[j], e1, mu2[j]));
                s0 += q0[j]; s1 += q1[j];
            }
        } else {
#pragma unroll
            for (int j = 0; j < 4; ++j) { q0[j] = 0.f; q1[j] = 0.f; }
        }
#pragma unroll
        for (int off = 16; off; off >>= 1) {
            s0 += __shfl_xor_sync(0xffffffffu, s0, off);
            s1 += __shfl_xor_sync(0xffffffffu, s1, off);
        }
        if (lane == 0) {
            wsum[buf][0][warp] = s0;
            wsum[buf][1][warp] = s1;
        }
        __syncthreads();

        float t0 = 0.f, t1 = 0.f;
#pragma unroll
        for (int w = 0; w < 8; ++w) {
            t0 += wsum[buf][0][w];
            t1 += wsum[buf][1][w];
        }
        float inv0, inv1;
        asm("rcp.approx.ftz.f32 %0, %1;" : "=f"(inv0) : "f"(t0));
        asm("rcp.approx.ftz.f32 %0, %1;" : "=f"(inv1) : "f"(t1));

        a0 = fmaf(q0[0], inv0, a0); a0 = fmaf(q1[0], inv1, a0);
        a1 = fmaf(q0[1], inv0, a1); a1 = fmaf(q1[1], inv1, a1);
        a2 = fmaf(q0[2], inv0, a2); a2 = fmaf(q1[2], inv1, a2);
        a3 = fmaf(q0[3], inv0, a3); a3 = fmaf(q1[3], inv1, a3);
    }

    if (active) {
        float4 o;
        o.x = __expf(a0 * 0.03125f);
        o.y = __expf(a1 * 0.03125f);
        o.z = __expf(a2 * 0.03125f);
        o.w = __expf(a3 * 0.03125f);
        *(float4*)(out + (size_t)n * C_CLS + c0) = o;
    }
}

// ---------------------------------------------------------------------------
extern "C" void kernel_launch(void* const* d_in, const int* in_sizes, int n_in,
                              void* d_out, int out_size)
{
    const float* X = (const float*)d_in[0];   // (4096, 1024)
    const float* W = (const float*)d_in[1];   // (2000, 1024)
    float* out = (float*)d_out;               // mu_out (4096,1000) ++ sigma (4096,1000)

    const int gemm_smem = 2 * STAGE_F * 4;    // 73728 B
    cudaFuncSetAttribute(gemm_kernel,
                         cudaFuncAttributeMaxDynamicSharedMemorySize, gemm_smem);
    gemm_kernel<<<dim3(16, 32), 256, gemm_smem>>>(X, W, out);
    sample_kernel<<<N_ROWS, 256>>>(out);
}